// round 6
// baseline (speedup 1.0000x reference)
#include <cuda_runtime.h>
#include <cstdint>

#define N_POS 4096
#define N_NEG 4096
#define N_NEU 2048
#define N_ROW (N_POS + N_NEG)            // 8192
#define DIM   512
#define ROW_BYTES (DIM * 4)              // 2048

#define THREADS 256
#define WARPS_PER_BLK (THREADS / 32)     // 8
#define ROW_BLOCKS (N_ROW / WARPS_PER_BLK)                 // 1024
#define NEU_BLOCKS ((N_NEU + THREADS - 1) / THREADS)       // 8
#define GRID (ROW_BLOCKS + NEU_BLOCKS)                     // 1032

#define SCALE (0.5f / (float)(N_POS + N_NEG + N_NEU))

__device__ float    g_accum = 0.0f;
__device__ unsigned g_count = 0u;

__device__ __forceinline__ float warp_sum(float x) {
    #pragma unroll
    for (int o = 16; o; o >>= 1)
        x += __shfl_xor_sync(0xFFFFFFFFu, x, o);
    return x;
}

__device__ __forceinline__ uint32_t smem_u32(const void* p) {
    return (uint32_t)__cvta_generic_to_shared(p);
}

__global__ __launch_bounds__(THREADS) void dcl_kernel(
    const float* __restrict__ emb,
    const int* __restrict__ pos_ids, const int* __restrict__ pos_dims,
    const int* __restrict__ neg_ids, const int* __restrict__ neg_dims,
    const int* __restrict__ neu_ids, const int* __restrict__ neu_dims,
    float* __restrict__ out)
{
    __shared__ alignas(16)  uint64_t mbar[WARPS_PER_BLK];
    __shared__ alignas(128) float    buf[WARPS_PER_BLK][DIM];   // 16 KB

    const int lane = threadIdx.x & 31;
    const int warp = threadIdx.x >> 5;

    float local = 0.0f;

    if (blockIdx.x < ROW_BLOCKS) {
        // ---- one row-constraint per warp, loaded via cp.async.bulk ----
        int w = blockIdx.x * WARPS_PER_BLK + warp;       // 0..8191
        bool positive = (w < N_POS);
        int idx = positive ? w : (w - N_POS);
        int id  = positive ? __ldg(pos_ids  + idx) : __ldg(neg_ids  + idx);
        int dim = positive ? __ldg(pos_dims + idx) : __ldg(neg_dims + idx);

        // init per-warp mbarrier (count = 1), then make visible block-wide
        uint32_t mb = smem_u32(&mbar[warp]);
        if (lane == 0) {
            asm volatile("mbarrier.init.shared::cta.b64 [%0], 1;"
                         :: "r"(mb) : "memory");
        }
        __syncthreads();

        // lane 0: arrive with expect_tx, then one 2KB bulk copy gmem->smem
        uint32_t dst = smem_u32(&buf[warp][0]);
        const void* src = (const void*)(emb + (size_t)id * DIM);
        if (lane == 0) {
            asm volatile(
                "mbarrier.arrive.expect_tx.shared::cta.b64 _, [%0], %1;"
                :: "r"(mb), "r"((uint32_t)ROW_BYTES) : "memory");
            asm volatile(
                "cp.async.bulk.shared::cta.global.mbarrier::complete_tx::bytes "
                "[%0], [%1], %2, [%3];"
                :: "r"(dst), "l"(src), "r"((uint32_t)ROW_BYTES), "r"(mb)
                : "memory");
        }

        // all lanes wait on this warp's barrier (phase 0, single shot)
        {
            uint32_t done;
            asm volatile(
                "{\n\t.reg .pred p;\n\t"
                "mbarrier.try_wait.parity.acquire.cta.shared::cta.b64 p, [%1], 0;\n\t"
                "selp.b32 %0, 1, 0, p;\n\t}"
                : "=r"(done) : "r"(mb) : "memory");
            if (!done) {
                asm volatile(
                    "{\n\t.reg .pred P1;\n\t"
                    "W%=:\n\t"
                    "mbarrier.try_wait.parity.acquire.cta.shared::cta.b64 P1, [%0], 0, 0x989680;\n\t"
                    "@P1 bra.uni D%=;\n\t"
                    "bra.uni W%=;\n\t"
                    "D%=:\n\t}"
                    :: "r"(mb) : "memory");
            }
        }

        // reduce |row| from smem: 4 x LDS.128 per lane, conflict-free
        const float4* f4 = reinterpret_cast<const float4*>(&buf[warp][0]);
        float4 a0 = f4[lane +  0];
        float4 a1 = f4[lane + 32];
        float4 a2 = f4[lane + 64];
        float4 a3 = f4[lane + 96];

        float s = fabsf(a0.x)+fabsf(a0.y)+fabsf(a0.z)+fabsf(a0.w)
                + fabsf(a1.x)+fabsf(a1.y)+fabsf(a1.z)+fabsf(a1.w)
                + fabsf(a2.x)+fabsf(a2.y)+fabsf(a2.z)+fabsf(a2.w)
                + fabsf(a3.x)+fabsf(a3.y)+fabsf(a3.z)+fabsf(a3.w);

        // target element straight from smem (only lane 0 needs it)
        float t = buf[warp][dim];

        s = warp_sum(s);

        if (lane == 0) {
            float at = fabsf(t);
            float sl = positive
                ? ((t <= 0.0f) ? (at + 0.1f) : (-0.1f * t))
                : ((t >= 0.0f) ? (at + 0.1f) : (-0.1f * at));
            local = sl + (s - at) * (0.1f / (float)(DIM - 1));
        }
    } else {
        // ---- neutral: one element per thread ----
        __syncthreads();   // match the row-path barrier (uniform per block anyway)
        int i = (blockIdx.x - ROW_BLOCKS) * THREADS + threadIdx.x;
        if (i < N_NEU) {
            int id  = __ldg(neu_ids + i);
            int dim = __ldg(neu_dims + i);
            local = 2.0f * fabsf(__ldg(emb + (size_t)id * DIM + dim));
        }
        local = warp_sum(local);
        if (lane != 0) local = 0.0f;
    }

    // ---- block reduce (lane0 of each warp holds a value) ----
    __shared__ float sh[WARPS_PER_BLK];
    if (lane == 0) sh[warp] = local;
    __syncthreads();

    if (threadIdx.x == 0) {
        float v = sh[0] + sh[1] + sh[2] + sh[3]
                + sh[4] + sh[5] + sh[6] + sh[7];
        atomicAdd(&g_accum, v);
        __threadfence();
        unsigned n = atomicAdd(&g_count, 1u);
        if (n == (unsigned)(GRID - 1)) {
            // last block: finalize and reset scratch for next graph replay
            __threadfence();
            float total = atomicExch(&g_accum, 0.0f);
            atomicExch(&g_count, 0u);
            out[0] = total * SCALE;
        }
    }
}

extern "C" void kernel_launch(void* const* d_in, const int* in_sizes, int n_in,
                              void* d_out, int out_size)
{
    const float* emb      = (const float*)d_in[0];
    const int*   pos_ids  = (const int*)d_in[1];
    const int*   pos_dims = (const int*)d_in[2];
    const int*   neg_ids  = (const int*)d_in[3];
    const int*   neg_dims = (const int*)d_in[4];
    const int*   neu_ids  = (const int*)d_in[5];
    const int*   neu_dims = (const int*)d_in[6];

    dcl_kernel<<<GRID, THREADS>>>(
        emb, pos_ids, pos_dims, neg_ids, neg_dims, neu_ids, neu_dims,
        (float*)d_out);
}